// round 5
// baseline (speedup 1.0000x reference)
#include <cuda_runtime.h>
#include <cuda_bf16.h>
#include <math.h>
#include <stdint.h>

#define NUM_O   5000
#define NUM_T   20000
#define DD      128
#define HH      512
#define GG      64
#define LL      5
#define K1      (3*DD)        // 384
#define N2      (2*HH+DD)     // 1152

typedef __nv_bfloat16 bf16;

// ================= scratch =================
__device__ float g_ov    [NUM_O * DD];
__device__ float g_pooled[NUM_O * HH];
__device__ float g_counts[NUM_O];
__device__ float g_invcnt[NUM_O];
__device__ float g_scores[NUM_O];
__device__ float g_gvec  [GG * DD];

__device__ bf16 g_ovh[NUM_O * DD], g_ovl[NUM_O * DD];
__device__ bf16 g_pvh[NUM_T * DD], g_pvl[NUM_T * DD];
__device__ bf16 g_hh [NUM_T * HH], g_hl [NUM_T * HH];
__device__ bf16 g_h2h[NUM_O * HH], g_h2l[NUM_O * HH];

__device__ bf16 g_w1h[LL * HH * K1], g_w1l[LL * HH * K1];
__device__ bf16 g_w2h[LL * N2 * HH], g_w2l[LL * N2 * HH];
__device__ bf16 g_w3h[LL * HH * HH], g_w3l[LL * HH * HH];
__device__ bf16 g_w4h[LL * DD * HH], g_w4l[LL * DD * HH];

__device__ __forceinline__ void f32split(float v, bf16& h, bf16& l) {
    h = __float2bfloat16(v);
    l = __float2bfloat16(v - __bfloat162float(h));
}
__device__ __forceinline__ uint32_t bfpack(bf16 a, bf16 b) {
    __nv_bfloat162 t; t.x = a; t.y = b;
    return *reinterpret_cast<uint32_t*>(&t);
}
__device__ __forceinline__ uint32_t smem_u32(const void* p) {
    uint32_t a;
    asm("{ .reg .u64 t; cvta.to.shared.u64 t, %1; cvt.u32.u64 %0, t; }" : "=r"(a) : "l"(p));
    return a;
}

// ================= glue =================
__global__ void zero_kernel(float* p, int n) {
    int i = blockIdx.x * blockDim.x + threadIdx.x;
    if (i < n) p[i] = 0.f;
}
__global__ void gather_ov_init(const float* __restrict__ obj_emb,
                               const int* __restrict__ objs,
                               bf16* __restrict__ ovh, bf16* __restrict__ ovl) {
    int i = blockIdx.x, d = threadIdx.x;
    float v = obj_emb[objs[i] * DD + d];
    bf16 h, l; f32split(v, h, l);
    ovh[i * DD + d] = h; ovl[i * DD + d] = l;
}
__global__ void gather_pv0(const float* __restrict__ pred_emb,
                           const int* __restrict__ trip,
                           bf16* __restrict__ pvh, bf16* __restrict__ pvl) {
    int i = blockIdx.x, d = threadIdx.x;
    int p = trip[3 * i + 1];
    float v = pred_emb[p * DD + d];
    bf16 h, l; f32split(v, h, l);
    pvh[i * DD + d] = h; pvl[i * DD + d] = l;
}
__global__ void count_kernel(const int* __restrict__ trip, float* __restrict__ counts) {
    int i = blockIdx.x * blockDim.x + threadIdx.x;
    if (i < NUM_T) {
        atomicAdd(&counts[trip[3 * i + 0]], 1.f);
        atomicAdd(&counts[trip[3 * i + 2]], 1.f);
    }
}
__global__ void inv_kernel(const float* __restrict__ counts, float* __restrict__ inv) {
    int i = blockIdx.x * blockDim.x + threadIdx.x;
    if (i < NUM_O) inv[i] = 1.f / fmaxf(counts[i], 1.f);
}
__global__ void wtrans_split(const float* __restrict__ w,
                             bf16* __restrict__ oh,
                             bf16* __restrict__ ol, int K, int N) {
    __shared__ float tile[32][33];
    int l = blockIdx.z;
    int k0 = blockIdx.y * 32, n0 = blockIdx.x * 32;
    const float* wl = w + (size_t)l * K * N;
    tile[threadIdx.y][threadIdx.x] = wl[(size_t)(k0 + threadIdx.y) * N + n0 + threadIdx.x];
    __syncthreads();
    int on = n0 + threadIdx.y, ok = k0 + threadIdx.x;
    float v = tile[threadIdx.x][threadIdx.y];
    bf16 h, lo; f32split(v, h, lo);
    size_t idx = ((size_t)l * N + on) * K + ok;
    oh[idx] = h; ol[idx] = lo;
}

// ================= HMMA GEMM =================
// C = relu(A @ B^T + bias), 3-term bf16 split, fp32 accum.
// A_MODE 0: Ah/Al [M,K]. 1: gathered (ov[s]|pv|ov[o]). 2: fp32 Af * inv[row], split on the fly.
// OUT_MODE 1: bf16 pair. 2: fp32 + bf16 pair. 3: smem-staged scatter (red.v4 + pv block).
#define BN   128
#define BK   32

#define CP_ASYNC16(dst, src, sz) \
    asm volatile("cp.async.cg.shared.global [%0], [%1], 16, %2;" :: "r"(dst), "l"(src), "r"(sz))
#define CP_COMMIT() asm volatile("cp.async.commit_group;")
#define LDSM_X4(R0,R1,R2,R3,ADDR) \
    asm volatile("ldmatrix.sync.aligned.m8n8.x4.shared.b16 {%0,%1,%2,%3}, [%4];" \
                 : "=r"(R0),"=r"(R1),"=r"(R2),"=r"(R3) : "r"(ADDR))
#define MMA16816(C,A0,A1,A2,A3,B0,B1) \
    asm volatile("mma.sync.aligned.m16n8k16.row.col.f32.bf16.bf16.f32 " \
                 "{%0,%1,%2,%3},{%4,%5,%6,%7},{%8,%9},{%0,%1,%2,%3};" \
                 : "+f"((C)[0]),"+f"((C)[1]),"+f"((C)[2]),"+f"((C)[3]) \
                 : "r"(A0),"r"(A1),"r"(A2),"r"(A3),"r"(B0),"r"(B1))
#define STS128(ADDR,A,B,C,D) \
    asm volatile("st.shared.v4.b32 [%0], {%1,%2,%3,%4};" :: "r"(ADDR),"r"(A),"r"(B),"r"(C),"r"(D))
#define REDV4(PTR,X,Y,Z,W) \
    asm volatile("red.global.add.v4.f32 [%0], {%1,%2,%3,%4};" :: "l"(PTR),"f"(X),"f"(Y),"f"(Z),"f"(W) : "memory")

__device__ __forceinline__ uint32_t sw_off(int row, int c) {
    return (uint32_t)(row * 64 + (((c ^ (row & 3))) << 4));
}

template <int A_MODE, int TBM>
__device__ __forceinline__ void ld_stage(
    uint32_t st,
    const bf16* __restrict__ Ah, const bf16* __restrict__ Al,
    const float* __restrict__ Af, const float* __restrict__ inv,
    const bf16* __restrict__ OVh, const bf16* __restrict__ OVl,
    const bf16* __restrict__ PVh, const bf16* __restrict__ PVl,
    const int* __restrict__ trip,
    const bf16* __restrict__ Bh, const bf16* __restrict__ Bl,
    int bm, int bn, int k0, int M, int K, int tid)
{
    constexpr uint32_t OFF_AL = TBM * 64;
    constexpr uint32_t OFF_BH = TBM * 128;
    constexpr uint32_t OFF_BL = TBM * 128 + 8192;
    int seg = k0 >> 7;
    int koff_base = k0 & 127;
    // ---- A ----
#pragma unroll
    for (int lin = tid; lin < TBM * 4; lin += 256) {
        int row = lin >> 2;
        int c   = lin & 3;
        uint32_t so = sw_off(row, c);
        int gr = bm + row;
        bool ok = gr < M;
        if (A_MODE == 2) {
            if (ok) {
                const float4* src = reinterpret_cast<const float4*>(Af + (size_t)gr * K + k0 + c * 8);
                float4 v0 = src[0], v1 = src[1];
                float s = __ldg(&inv[gr]);
                bf16 hb[8], lb[8];
                float vals[8] = {v0.x*s, v0.y*s, v0.z*s, v0.w*s, v1.x*s, v1.y*s, v1.z*s, v1.w*s};
#pragma unroll
                for (int j = 0; j < 8; j++) f32split(vals[j], hb[j], lb[j]);
                STS128(st + so, bfpack(hb[0],hb[1]), bfpack(hb[2],hb[3]), bfpack(hb[4],hb[5]), bfpack(hb[6],hb[7]));
                STS128(st + OFF_AL + so, bfpack(lb[0],lb[1]), bfpack(lb[2],lb[3]), bfpack(lb[4],lb[5]), bfpack(lb[6],lb[7]));
            } else {
                STS128(st + so, 0u, 0u, 0u, 0u);
                STS128(st + OFF_AL + so, 0u, 0u, 0u, 0u);
            }
        } else {
            uint32_t sz = ok ? 16u : 0u;
            const char *sh, *sl;
            if (A_MODE == 0) {
                size_t srow = ok ? (size_t)gr : 0;
                sh = (const char*)(Ah + srow * K + k0 + c * 8);
                sl = (const char*)(Al + srow * K + k0 + c * 8);
            } else {
                int gi = ok ? gr : 0;
                int koff = koff_base + c * 8;
                size_t off;
                if (seg == 0) {
                    int s = __ldg(&trip[3 * gi + 0]);
                    off = (size_t)s * DD + koff;
                    sh = (const char*)(OVh + off); sl = (const char*)(OVl + off);
                } else if (seg == 1) {
                    off = (size_t)gi * DD + koff;
                    sh = (const char*)(PVh + off); sl = (const char*)(PVl + off);
                } else {
                    int o = __ldg(&trip[3 * gi + 2]);
                    off = (size_t)o * DD + koff;
                    sh = (const char*)(OVh + off); sl = (const char*)(OVl + off);
                }
            }
            CP_ASYNC16(st + so, sh, sz);
            CP_ASYNC16(st + OFF_AL + so, sl, sz);
        }
    }
    // ---- B ----
#pragma unroll
    for (int lin = tid; lin < 512; lin += 256) {
        int row = lin >> 2;
        int c   = lin & 3;
        uint32_t so = sw_off(row, c);
        int gr = bn + row;
        const char* sh = (const char*)(Bh + (size_t)gr * K + k0 + c * 8);
        const char* sl = (const char*)(Bl + (size_t)gr * K + k0 + c * 8);
        CP_ASYNC16(st + OFF_BH + so, sh, 16u);
        CP_ASYNC16(st + OFF_BL + so, sl, 16u);
    }
}

template <int A_MODE, int OUT_MODE, int TBM>
__global__ void __launch_bounds__(256)
gemm_hmma(const bf16* __restrict__ Ah, const bf16* __restrict__ Al,
          const float* __restrict__ Af, const float* __restrict__ inv,
          const bf16* __restrict__ OVh, const bf16* __restrict__ OVl,
          const bf16* __restrict__ PVh, const bf16* __restrict__ PVl,
          const int* __restrict__ trip,
          const bf16* __restrict__ Bh, const bf16* __restrict__ Bl,
          const float* __restrict__ bias,
          float* __restrict__ Cf,
          bf16* __restrict__ Ch, bf16* __restrict__ Cl,
          float* __restrict__ pooled,
          bf16* __restrict__ Pvh, bf16* __restrict__ Pvl,
          int M, int N, int K)
{
    constexpr uint32_t OFF_AL = TBM * 64;
    constexpr uint32_t OFF_BH = TBM * 128;
    constexpr uint32_t OFF_BL = TBM * 128 + 8192;
    constexpr uint32_t STAGE  = TBM * 128 + 16384;
    constexpr int NWM = (TBM == 128) ? 2 : 1;   // warps along m
    constexpr int NT  = (TBM == 128) ? 4 : 2;   // n8 tiles per warp

    extern __shared__ char smem[];
    uint32_t sb = smem_u32(smem);

    int tid = threadIdx.x;
    int wid = tid >> 5, lane = tid & 31;
    int wm = (wid % NWM) * 64;
    int wn = (wid / NWM) * (NT * 8);
    int bm = blockIdx.y * TBM;
    int bn = blockIdx.x * BN;
    const int NC = K / BK;

    float acc[4][NT][4];
#pragma unroll
    for (int i = 0; i < 4; i++)
#pragma unroll
        for (int j = 0; j < NT; j++)
#pragma unroll
            for (int r = 0; r < 4; r++) acc[i][j][r] = 0.f;

    int lrow8 = (lane & 7) + ((lane >> 3) & 1) * 8;
    int lchunk = (lane >> 4);

    ld_stage<A_MODE, TBM>(sb, Ah, Al, Af, inv, OVh, OVl, PVh, PVl, trip, Bh, Bl, bm, bn, 0, M, K, tid);
    CP_COMMIT();

    for (int kc = 0; kc < NC; kc++) {
        if (kc + 1 < NC) {
            ld_stage<A_MODE, TBM>(sb + ((kc + 1) & 1) * STAGE, Ah, Al, Af, inv, OVh, OVl, PVh, PVl,
                                  trip, Bh, Bl, bm, bn, (kc + 1) * BK, M, K, tid);
            CP_COMMIT();
            asm volatile("cp.async.wait_group 1;");
        } else {
            asm volatile("cp.async.wait_group 0;");
        }
        __syncthreads();

        uint32_t sa = sb + (kc & 1) * STAGE;
#pragma unroll
        for (int ks = 0; ks < 2; ks++) {
            int c0 = ks * 2;
            uint32_t ah[4][4], al[4][4], bh[NT][2], bl[NT][2];
#pragma unroll
            for (int mt = 0; mt < 4; mt++) {
                int row = wm + mt * 16 + lrow8;
                uint32_t addr = sa + sw_off(row, c0 + lchunk);
                LDSM_X4(ah[mt][0], ah[mt][1], ah[mt][2], ah[mt][3], addr);
            }
#pragma unroll
            for (int np = 0; np < NT / 2; np++) {
                int row = wn + np * 16 + lrow8;
                uint32_t addr = sa + OFF_BH + sw_off(row, c0 + lchunk);
                uint32_t r0, r1, r2, r3;
                LDSM_X4(r0, r1, r2, r3, addr);
                bh[2*np][0] = r0; bh[2*np+1][0] = r1;
                bh[2*np][1] = r2; bh[2*np+1][1] = r3;
            }
#pragma unroll
            for (int mt = 0; mt < 4; mt++)
#pragma unroll
                for (int nt = 0; nt < NT; nt++)
                    MMA16816(acc[mt][nt], ah[mt][0], ah[mt][1], ah[mt][2], ah[mt][3],
                             bh[nt][0], bh[nt][1]);
#pragma unroll
            for (int np = 0; np < NT / 2; np++) {
                int row = wn + np * 16 + lrow8;
                uint32_t addr = sa + OFF_BL + sw_off(row, c0 + lchunk);
                uint32_t r0, r1, r2, r3;
                LDSM_X4(r0, r1, r2, r3, addr);
                bl[2*np][0] = r0; bl[2*np+1][0] = r1;
                bl[2*np][1] = r2; bl[2*np+1][1] = r3;
            }
#pragma unroll
            for (int mt = 0; mt < 4; mt++)
#pragma unroll
                for (int nt = 0; nt < NT; nt++)
                    MMA16816(acc[mt][nt], ah[mt][0], ah[mt][1], ah[mt][2], ah[mt][3],
                             bl[nt][0], bl[nt][1]);
#pragma unroll
            for (int mt = 0; mt < 4; mt++) {
                int row = wm + mt * 16 + lrow8;
                uint32_t addr = sa + OFF_AL + sw_off(row, c0 + lchunk);
                LDSM_X4(al[mt][0], al[mt][1], al[mt][2], al[mt][3], addr);
            }
#pragma unroll
            for (int mt = 0; mt < 4; mt++)
#pragma unroll
                for (int nt = 0; nt < NT; nt++)
                    MMA16816(acc[mt][nt], al[mt][0], al[mt][1], al[mt][2], al[mt][3],
                             bh[nt][0], bh[nt][1]);
        }
        __syncthreads();
    }

    int r = lane >> 2, q = lane & 3;

    if (OUT_MODE == 3) {
        // stage bias+relu'd tile to smem (128x128 fp32 = 64KB), then scatter
#pragma unroll
        for (int mt = 0; mt < 4; mt++) {
            int lr0 = wm + mt * 16 + r;
#pragma unroll
            for (int nt = 0; nt < NT; nt++) {
                int lc = wn + nt * 8 + q * 2;
                int col = bn + lc;
                float b0 = bias[col], b1 = bias[col + 1];
                float2 v0 = make_float2(fmaxf(acc[mt][nt][0] + b0, 0.f), fmaxf(acc[mt][nt][1] + b1, 0.f));
                float2 v1 = make_float2(fmaxf(acc[mt][nt][2] + b0, 0.f), fmaxf(acc[mt][nt][3] + b1, 0.f));
                *reinterpret_cast<float2*>(smem + ((size_t)lr0 * 128 + lc) * 4) = v0;
                *reinterpret_cast<float2*>(smem + ((size_t)(lr0 + 8) * 128 + lc) * 4) = v1;
            }
        }
        __syncthreads();
        int row = tid >> 1;                 // 0..127
        int half = (tid & 1) * 64;          // col half
        int gr = bm + row;
        if (gr < M) {
            const float* srow = reinterpret_cast<const float*>(smem) + (size_t)row * 128 + half;
            if (bn == 512) {
                // pv block: cols 512..639
#pragma unroll
                for (int i = 0; i < 16; i++) {
                    float4 v = *reinterpret_cast<const float4*>(srow + i * 4);
                    bf16 h0,l0,h1,l1,h2,l2,h3,l3;
                    f32split(v.x,h0,l0); f32split(v.y,h1,l1); f32split(v.z,h2,l2); f32split(v.w,h3,l3);
                    uint2 hp = make_uint2(bfpack(h0,h1), bfpack(h2,h3));
                    uint2 lp = make_uint2(bfpack(l0,l1), bfpack(l2,l3));
                    int pc = half + i * 4;
                    *reinterpret_cast<uint2*>(Pvh + (size_t)gr * DD + pc) = hp;
                    *reinterpret_cast<uint2*>(Pvl + (size_t)gr * DD + pc) = lp;
                }
            } else {
                int obj = __ldg(&trip[3 * gr + ((bn < 512) ? 0 : 2)]);
                float* dst = pooled + (size_t)obj * HH + ((bn < 512) ? bn : bn - 640) + half;
#pragma unroll
                for (int i = 0; i < 16; i++) {
                    float4 v = *reinterpret_cast<const float4*>(srow + i * 4);
                    REDV4(dst + i * 4, v.x, v.y, v.z, v.w);
                }
            }
        }
        return;
    }

#pragma unroll
    for (int mt = 0; mt < 4; mt++) {
        int row0 = bm + wm + mt * 16 + r;
        int row1 = row0 + 8;
#pragma unroll
        for (int nt = 0; nt < NT; nt++) {
            int col = bn + wn + nt * 8 + q * 2;
            float b0 = bias[col], b1 = bias[col + 1];
            float v00 = fmaxf(acc[mt][nt][0] + b0, 0.f);
            float v01 = fmaxf(acc[mt][nt][1] + b1, 0.f);
            float v10 = fmaxf(acc[mt][nt][2] + b0, 0.f);
            float v11 = fmaxf(acc[mt][nt][3] + b1, 0.f);
            bf16 h0, l0, h1, l1;
            if (row0 < M) {
                if (OUT_MODE == 2)
                    *reinterpret_cast<float2*>(Cf + (size_t)row0 * N + col) = make_float2(v00, v01);
                f32split(v00, h0, l0); f32split(v01, h1, l1);
                *reinterpret_cast<uint32_t*>(Ch + (size_t)row0 * N + col) = bfpack(h0, h1);
                *reinterpret_cast<uint32_t*>(Cl + (size_t)row0 * N + col) = bfpack(l0, l1);
            }
            if (row1 < M) {
                if (OUT_MODE == 2)
                    *reinterpret_cast<float2*>(Cf + (size_t)row1 * N + col) = make_float2(v10, v11);
                f32split(v10, h0, l0); f32split(v11, h1, l1);
                *reinterpret_cast<uint32_t*>(Ch + (size_t)row1 * N + col) = bfpack(h0, h1);
                *reinterpret_cast<uint32_t*>(Cl + (size_t)row1 * N + col) = bfpack(l0, l1);
            }
        }
    }
}

// ================= attention epilogue =================
__global__ void scores_kernel(const float* __restrict__ ov,
                              const float* __restrict__ att_w,
                              const float* __restrict__ att_b,
                              float* __restrict__ scores) {
    int gid = blockIdx.x * blockDim.x + threadIdx.x;
    int w = gid >> 5, lane = gid & 31;
    if (w >= NUM_O) return;
    float sum = 0.f;
#pragma unroll
    for (int d = lane; d < DD; d += 32) sum += ov[(size_t)w * DD + d] * att_w[d];
#pragma unroll
    for (int off = 16; off; off >>= 1) sum += __shfl_down_sync(0xffffffff, sum, off);
    if (lane == 0) scores[w] = sum + att_b[0];
}

__global__ void segment_kernel(const float* __restrict__ scores,
                               const int* __restrict__ img,
                               const float* __restrict__ ov,
                               float* __restrict__ gvec) {
    int g = blockIdx.x, t = threadIdx.x;   // 128 threads
    __shared__ float sred[128];
    __shared__ int ired[128];

    float m = -3.4e38f;
    int lo = NUM_O, hi = -1;
    for (int i = t; i < NUM_O; i += 128) {
        if (img[i] == g) {
            m = fmaxf(m, scores[i]);
            lo = min(lo, i);
            hi = max(hi, i);
        }
    }
    sred[t] = m; __syncthreads();
    for (int s = 64; s > 0; s >>= 1) { if (t < s) sred[t] = fmaxf(sred[t], sred[t + s]); __syncthreads(); }
    m = sred[0]; __syncthreads();
    ired[t] = lo; __syncthreads();
    for (int s = 64; s > 0; s >>= 1) { if (t < s) ired[t] = min(ired[t], ired[t + s]); __syncthreads(); }
    lo = ired[0]; __syncthreads();
    ired[t] = hi; __syncthreads();
    for (int s = 64; s > 0; s >>= 1) { if (t < s) ired[t] = max(ired[t], ired[t + s]); __syncthreads(); }
    hi = ired[0]; __syncthreads();

    float z = 0.f;
    for (int i = lo + t; i <= hi; i += 128)
        if (img[i] == g) z += expf(scores[i] - m);
    sred[t] = z; __syncthreads();
    for (int s = 64; s > 0; s >>= 1) { if (t < s) sred[t] += sred[t + s]; __syncthreads(); }
    z = sred[0];
    float invz = 1.f / z;

    float acc = 0.f;
    for (int i = lo; i <= hi; i++) {
        if (img[i] == g)
            acc += expf(scores[i] - m) * invz * ov[(size_t)i * DD + t];
    }
    gvec[g * DD + t] = acc;
}

__global__ void concat_kernel(const float* __restrict__ ov,
                              const float* __restrict__ gvec,
                              const int* __restrict__ img,
                              float* __restrict__ out) {
    int i = blockIdx.x, t = threadIdx.x;   // 256 threads
    if (t < DD) out[(size_t)i * 256 + t] = ov[(size_t)i * DD + t];
    else        out[(size_t)i * 256 + t] = gvec[img[i] * DD + (t - DD)];
}

// ================= launch =================
extern "C" void kernel_launch(void* const* d_in, const int* in_sizes, int n_in,
                              void* d_out, int out_size) {
    const int*   objs     = (const int*)d_in[0];
    const int*   trip     = (const int*)d_in[1];
    const int*   img      = (const int*)d_in[2];
    const float* obj_emb  = (const float*)d_in[3];
    const float* pred_emb = (const float*)d_in[4];
    const float* n1w1     = (const float*)d_in[5];
    const float* n1b1     = (const float*)d_in[6];
    const float* n1w2     = (const float*)d_in[7];
    const float* n1b2     = (const float*)d_in[8];
    const float* n2w1     = (const float*)d_in[9];
    const float* n2b1     = (const float*)d_in[10];
    const float* n2w2     = (const float*)d_in[11];
    const float* n2b2     = (const float*)d_in[12];
    const float* att_w    = (const float*)d_in[13];
    const float* att_b    = (const float*)d_in[14];
    float* out = (float*)d_out;

    float *ov, *pooled, *counts, *inv, *scores, *gvec;
    bf16 *ovh, *ovl, *pvh, *pvl, *hh, *hl, *h2h, *h2l;
    bf16 *w1h, *w1l, *w2h, *w2l, *w3h, *w3l, *w4h, *w4l;
    cudaGetSymbolAddress((void**)&ov,     g_ov);
    cudaGetSymbolAddress((void**)&pooled, g_pooled);
    cudaGetSymbolAddress((void**)&counts, g_counts);
    cudaGetSymbolAddress((void**)&inv,    g_invcnt);
    cudaGetSymbolAddress((void**)&scores, g_scores);
    cudaGetSymbolAddress((void**)&gvec,   g_gvec);
    cudaGetSymbolAddress((void**)&ovh, g_ovh); cudaGetSymbolAddress((void**)&ovl, g_ovl);
    cudaGetSymbolAddress((void**)&pvh, g_pvh); cudaGetSymbolAddress((void**)&pvl, g_pvl);
    cudaGetSymbolAddress((void**)&hh,  g_hh);  cudaGetSymbolAddress((void**)&hl,  g_hl);
    cudaGetSymbolAddress((void**)&h2h, g_h2h); cudaGetSymbolAddress((void**)&h2l, g_h2l);
    cudaGetSymbolAddress((void**)&w1h, g_w1h); cudaGetSymbolAddress((void**)&w1l, g_w1l);
    cudaGetSymbolAddress((void**)&w2h, g_w2h); cudaGetSymbolAddress((void**)&w2l, g_w2l);
    cudaGetSymbolAddress((void**)&w3h, g_w3h); cudaGetSymbolAddress((void**)&w3l, g_w3l);
    cudaGetSymbolAddress((void**)&w4h, g_w4h); cudaGetSymbolAddress((void**)&w4l, g_w4l);

    const int SMEM128 = 65536;   // 2 stages (64KB) == staging tile
    const int SMEM64  = 49152;
    cudaFuncSetAttribute(gemm_hmma<1,1,128>, cudaFuncAttributeMaxDynamicSharedMemorySize, SMEM128);
    cudaFuncSetAttribute(gemm_hmma<0,3,128>, cudaFuncAttributeMaxDynamicSharedMemorySize, SMEM128);
    cudaFuncSetAttribute(gemm_hmma<2,1,64>,  cudaFuncAttributeMaxDynamicSharedMemorySize, SMEM64);
    cudaFuncSetAttribute(gemm_hmma<0,2,64>,  cudaFuncAttributeMaxDynamicSharedMemorySize, SMEM64);

    wtrans_split<<<dim3(HH/32, K1/32, LL), dim3(32,32)>>>(n1w1, w1h, w1l, K1, HH);
    wtrans_split<<<dim3(N2/32, HH/32, LL), dim3(32,32)>>>(n1w2, w2h, w2l, HH, N2);
    wtrans_split<<<dim3(HH/32, HH/32, LL), dim3(32,32)>>>(n2w1, w3h, w3l, HH, HH);
    wtrans_split<<<dim3(DD/32, HH/32, LL), dim3(32,32)>>>(n2w2, w4h, w4l, HH, DD);

    gather_ov_init<<<NUM_O, DD>>>(obj_emb, objs, ovh, ovl);
    gather_pv0<<<NUM_T, DD>>>(pred_emb, trip, pvh, pvl);
    zero_kernel<<<(NUM_O + 255) / 256, 256>>>(counts, NUM_O);
    count_kernel<<<(NUM_T + 255) / 256, 256>>>(trip, counts);
    inv_kernel<<<(NUM_O + 255) / 256, 256>>>(counts, inv);

    const int mT   = (NUM_T + 127) / 128;   // 157
    const int mO64 = (NUM_O + 63) / 64;     // 79

    for (int l = 0; l < LL; l++) {
        // GEMM1: h = relu(gather(ov,pv) @ w1 + b1) [20000,512,K=384]
        gemm_hmma<1,1,128><<<dim3(HH/BN, mT), 256, SMEM128>>>(
            nullptr, nullptr, nullptr, nullptr, ovh, ovl, pvh, pvl, trip,
            w1h + (size_t)l*HH*K1, w1l + (size_t)l*HH*K1, n1b1 + (size_t)l*HH,
            nullptr, hh, hl, nullptr, nullptr, nullptr, NUM_T, HH, K1);

        zero_kernel<<<(NUM_O * HH + 255) / 256, 256>>>(pooled, NUM_O * HH);

        // GEMM2: fused smem-staged scatter (red.v4) [20000,1152,K=512]
        gemm_hmma<0,3,128><<<dim3(N2/BN, mT), 256, SMEM128>>>(
            hh, hl, nullptr, nullptr, nullptr, nullptr, nullptr, nullptr, trip,
            w2h + (size_t)l*N2*HH, w2l + (size_t)l*N2*HH, n1b2 + (size_t)l*N2,
            nullptr, nullptr, nullptr, pooled, pvh, pvl, NUM_T, N2, HH);

        // GEMM3: h2 = relu((pooled*inv) @ w3 + b3), fused scale+split loader [5000,512,K=512]
        gemm_hmma<2,1,64><<<dim3(HH/BN, mO64), 256, SMEM64>>>(
            nullptr, nullptr, pooled, inv, nullptr, nullptr, nullptr, nullptr, trip,
            w3h + (size_t)l*HH*HH, w3l + (size_t)l*HH*HH, n2b1 + (size_t)l*HH,
            nullptr, h2h, h2l, nullptr, nullptr, nullptr, NUM_O, HH, HH);

        // GEMM4: ov = relu(h2 @ w4 + b4), fp32 + bf16 pair [5000,128,K=512]
        gemm_hmma<0,2,64><<<dim3(DD/BN, mO64), 256, SMEM64>>>(
            h2h, h2l, nullptr, nullptr, nullptr, nullptr, nullptr, nullptr, trip,
            w4h + (size_t)l*DD*HH, w4l + (size_t)l*DD*HH, n2b2 + (size_t)l*DD,
            ov, ovh, ovl, nullptr, nullptr, nullptr, NUM_O, DD, HH);
    }

    scores_kernel<<<(NUM_O * 32 + 255) / 256, 256>>>(ov, att_w, att_b, scores);
    segment_kernel<<<GG, 128>>>(scores, img, ov, gvec);
    concat_kernel<<<NUM_O, 256>>>(ov, gvec, img, out);
}